// round 2
// baseline (speedup 1.0000x reference)
#include <cuda_runtime.h>
#include <cstdint>

// ToeplitzLinear: Y[b,i] = sum_j X[b,j] * vals[(4095 - i) + j]
// => GEMM D[m,n] = sum_k A[m,k] * B[k,n] with B[k,n] = vals[k - n + 4095]
// M = 8192 (batch), N = 4096 (out), K = 4096 (in). Output fp32 [8192, 4096].
//
// tf32 tensor-core GEMM (mma.sync.m16n8k8), B tile synthesized from a
// 159-element vals window in SMEM (Toeplitz structure -> no W in GMEM).

#define M_DIM   8192
#define N_DIM   4096
#define K_DIM   4096

#define BM 128
#define BN 128
#define BK 32
#define SK 33          // padded A row stride (words) to avoid bank conflicts
#define SV_LEN 160     // 128 + 32 - 1 = 159, padded

__device__ __forceinline__ uint32_t f2tf32(float f) {
    uint32_t r;
    asm("cvt.rna.tf32.f32 %0, %1;" : "=r"(r) : "f"(f));
    return r;
}

__device__ __forceinline__ void mma_tf32(float c[4], const uint32_t a[4],
                                         uint32_t b0, uint32_t b1) {
    asm volatile(
        "mma.sync.aligned.m16n8k8.row.col.f32.tf32.tf32.f32 "
        "{%0,%1,%2,%3}, {%4,%5,%6,%7}, {%8,%9}, {%0,%1,%2,%3};"
        : "+f"(c[0]), "+f"(c[1]), "+f"(c[2]), "+f"(c[3])
        : "r"(a[0]), "r"(a[1]), "r"(a[2]), "r"(a[3]), "r"(b0), "r"(b1));
}

__global__ void __launch_bounds__(256, 1)
toeplitz_tf32_kernel(const float* __restrict__ x,
                     const float* __restrict__ vals,
                     float* __restrict__ out) {
    __shared__ uint32_t sA[BM * SK];   // X tile as tf32 bit patterns
    __shared__ uint32_t sv[SV_LEN];    // vals window as tf32

    const int tid   = threadIdx.x;
    const int wid   = tid >> 5;
    const int lane  = tid & 31;
    const int g     = lane >> 2;   // groupID (0..7)
    const int tig   = lane & 3;    // thread-in-group (0..3)
    const int warpM = wid & 3;     // 4 warps along M (32 rows each)
    const int warpN = wid >> 2;    // 2 warps along N (64 cols each)

    const int m0 = blockIdx.y * BM;
    const int n0 = blockIdx.x * BN;

    float acc[2][8][4];
#pragma unroll
    for (int mm = 0; mm < 2; mm++)
#pragma unroll
        for (int nn = 0; nn < 8; nn++)
#pragma unroll
            for (int r = 0; r < 4; r++) acc[mm][nn][r] = 0.0f;

    // A-tile loader mapping: each thread loads 4x float4 (16 floats)
    const int lm = tid >> 3;           // 0..31
    const int lk = (tid & 7) * 4;      // 0,4,...,28

    // vals window base for this CTA (always in [0, 8190] for all tiles):
    // sv[t] = vals[k0 - n0 + 3968 + t],  B[k][n] = sv[(k-k0) + 127 - (n-n0)]
    const int vbase0 = 3968 - n0;

#pragma unroll 1
    for (int k0 = 0; k0 < K_DIM; k0 += BK) {
        // ---- load X tile (convert fp32 -> tf32 rna) ----
#pragma unroll
        for (int i = 0; i < 4; i++) {
            const int m = lm + i * 32;
            float4 v = *reinterpret_cast<const float4*>(
                x + (size_t)(m0 + m) * K_DIM + k0 + lk);
            const int b = m * SK + lk;
            sA[b + 0] = f2tf32(v.x);
            sA[b + 1] = f2tf32(v.y);
            sA[b + 2] = f2tf32(v.z);
            sA[b + 3] = f2tf32(v.w);
        }
        // ---- load vals window ----
        if (tid < 159) sv[tid] = f2tf32(vals[vbase0 + k0 + tid]);
        __syncthreads();

#pragma unroll
        for (int ks = 0; ks < 4; ks++) {
            uint32_t a[2][4];
#pragma unroll
            for (int mm = 0; mm < 2; mm++) {
                const int rbase = warpM * 32 + mm * 16 + g;
                const int kb = ks * 8 + tig;
                a[mm][0] = sA[rbase * SK + kb];
                a[mm][1] = sA[(rbase + 8) * SK + kb];
                a[mm][2] = sA[rbase * SK + kb + 4];
                a[mm][3] = sA[(rbase + 8) * SK + kb + 4];
            }
#pragma unroll
            for (int nn = 0; nn < 8; nn++) {
                const int bi = ks * 8 + tig + 127 - warpN * 64 - nn * 8 - g;
                const uint32_t b0 = sv[bi];
                const uint32_t b1 = sv[bi + 4];
                mma_tf32(acc[0][nn], a[0], b0, b1);
                mma_tf32(acc[1][nn], a[1], b0, b1);
            }
        }
        __syncthreads();
    }

    // ---- epilogue: c0/c1 are adjacent columns -> float2 stores ----
#pragma unroll
    for (int mm = 0; mm < 2; mm++) {
        const int row = m0 + warpM * 32 + mm * 16 + g;
#pragma unroll
        for (int nn = 0; nn < 8; nn++) {
            const int col = n0 + warpN * 64 + nn * 8 + tig * 2;
            *reinterpret_cast<float2*>(out + (size_t)row * N_DIM + col) =
                make_float2(acc[mm][nn][0], acc[mm][nn][1]);
            *reinterpret_cast<float2*>(out + (size_t)(row + 8) * N_DIM + col) =
                make_float2(acc[mm][nn][2], acc[mm][nn][3]);
        }
    }
}

extern "C" void kernel_launch(void* const* d_in, const int* in_sizes, int n_in,
                              void* d_out, int out_size) {
    const float* x    = (const float*)d_in[0];
    const float* vals = (const float*)d_in[1];
    float* out        = (float*)d_out;

    dim3 grid(N_DIM / BN, M_DIM / BM);   // x = n-tile fastest -> X tile L2 reuse
    dim3 block(256);
    toeplitz_tf32_kernel<<<grid, block>>>(x, vals, out);
}

// round 4
// speedup vs baseline: 1.2872x; 1.2872x over previous
#include <cuda_runtime.h>
#include <cstdint>

// ToeplitzLinear: D[m,n] = sum_k X[m,k] * vals[4095 - n + k]
// Legacy tf32 mma.sync (tcgen05 unavailable: harness PTX targets sm_103).
// Key ideas: conflict-free 144B-padded A smem, Toeplitz diagonal B-fragment
// register reuse (22 LDS instead of 64 per warp-iter), cp.async 3-stage
// pipeline from tf32-pre-rounded scratch, 2 CTAs/SM.

#define M_DIM 8192
#define N_DIM 4096
#define K_DIM 4096
#define BM 128
#define BN 128
#define BK 32
#define NITER (K_DIM / BK)       // 128
#define THREADS 256

#define A_ROW_WORDS 36           // 32 data + 4 pad -> bank = 4g+tig (conflict-free)
#define A_STAGE_BYTES (BM * A_ROW_WORDS * 4)   // 18432
#define SV_OFF (3 * A_STAGE_BYTES)             // 55296
#define SMEM_TOTAL (SV_OFF + 2 * 160 * 4)      // 56576

__device__ uint32_t g_xtf[(size_t)M_DIM * K_DIM];   // tf32-rounded X bits

__device__ __forceinline__ uint32_t f2tf32(float f) {
    uint32_t r;
    asm("cvt.rna.tf32.f32 %0, %1;" : "=r"(r) : "f"(f));
    return r;
}
__device__ __forceinline__ uint32_t smem_u32(const void* p) {
    uint32_t a;
    asm("{ .reg .u64 t; cvta.to.shared.u64 t, %1; cvt.u32.u64 %0, t; }"
        : "=r"(a) : "l"(p));
    return a;
}
__device__ __forceinline__ void cp16(uint32_t saddr, const void* g) {
    asm volatile("cp.async.cg.shared.global [%0], [%1], 16;"
                 :: "r"(saddr), "l"(g) : "memory");
}
__device__ __forceinline__ void cp_commit() {
    asm volatile("cp.async.commit_group;" ::: "memory");
}
template <int N>
__device__ __forceinline__ void cp_wait() {
    asm volatile("cp.async.wait_group %0;" :: "n"(N) : "memory");
}
__device__ __forceinline__ void mma_tf32(float c[4], const uint32_t a[4],
                                         uint32_t b0, uint32_t b1) {
    asm volatile(
        "mma.sync.aligned.m16n8k8.row.col.f32.tf32.tf32.f32 "
        "{%0,%1,%2,%3}, {%4,%5,%6,%7}, {%8,%9}, {%0,%1,%2,%3};"
        : "+f"(c[0]), "+f"(c[1]), "+f"(c[2]), "+f"(c[3])
        : "r"(a[0]), "r"(a[1]), "r"(a[2]), "r"(a[3]), "r"(b0), "r"(b1));
}

// Pre-pass: round X fp32 -> tf32 bits once (zero-mean rounding, rel_err ~3e-4)
__global__ void __launch_bounds__(256) cvt_x_kernel(const float* __restrict__ x) {
    size_t i = (size_t)blockIdx.x * 256 + threadIdx.x;
    float4 v = reinterpret_cast<const float4*>(x)[i];
    uint4 u;
    u.x = f2tf32(v.x); u.y = f2tf32(v.y); u.z = f2tf32(v.z); u.w = f2tf32(v.w);
    reinterpret_cast<uint4*>(g_xtf)[i] = u;
}

__device__ __forceinline__ void issue_a(int u, int tid, uint32_t sb, int m0) {
    const uint32_t sbase = sb + (u % 3) * A_STAGE_BYTES;
#pragma unroll
    for (int i = 0; i < 4; i++) {
        const int cid = tid + THREADS * i;    // 0..1023
        const int m = cid >> 3;                // row 0..127
        const int j = cid & 7;                 // 16B chunk 0..7
        const void* g = g_xtf + (size_t)(m0 + m) * K_DIM + u * BK + j * 4;
        cp16(sbase + m * (A_ROW_WORDS * 4) + j * 16, g);
    }
}

__global__ void __launch_bounds__(THREADS, 2)
toeplitz_mma_kernel(const float* __restrict__ vals, float* __restrict__ out) {
    extern __shared__ char smem[];
    const uint32_t sb = smem_u32(smem);
    const int tid = threadIdx.x;
    const int wid = tid >> 5;
    const int lane = tid & 31;
    const int g = lane >> 2;       // 0..7
    const int tig = lane & 3;      // 0..3
    const int warpM = wid & 3;     // 4 warps along M
    const int warpN = wid >> 2;    // 2 warps along N

    const int n0 = blockIdx.x * BN;   // n fastest -> X tile L2 reuse
    const int m0 = blockIdx.y * BM;
    const int vbase = 3968 - n0;      // sv_t[i] = vals[vbase + 32t + i], i<159

    float acc[2][8][4];
#pragma unroll
    for (int mm = 0; mm < 2; mm++)
#pragma unroll
        for (int nn = 0; nn < 8; nn++)
#pragma unroll
            for (int r = 0; r < 4; r++) acc[mm][nn][r] = 0.0f;

    uint32_t* svs = reinterpret_cast<uint32_t*>(smem + SV_OFF);

    // prologue: vals window 0, A stages 0 and 1
    if (tid < 159) svs[tid] = f2tf32(__ldg(vals + vbase + tid));
    issue_a(0, tid, sb, m0);
    cp_commit();
    issue_a(1, tid, sb, m0);
    cp_commit();

    // per-lane base for Toeplitz B fragments: bi = P + 8(ks-nn), P-56 >= 0
    const int Pl = tig - g + 71 - warpN * 64;

#pragma unroll 1
    for (int t = 0; t < NITER; t++) {
        cp_wait<1>();          // stage t landed (this thread's groups)
        __syncthreads();       // visible to all; sv[t&1] from last interval ready

        // prefetch vals window t+1 into the other buffer (post-sync: no race)
        if (t + 1 < NITER && tid < 159)
            svs[((t + 1) & 1) * 160 + tid] =
                f2tf32(__ldg(vals + vbase + 32 * (t + 1) + tid));
        // prefetch A stage t+2 (3-stage ring; commit always to keep FIFO count)
        if (t + 2 < NITER) issue_a(t + 2, tid, sb, m0);
        cp_commit();

        const uint32_t* svb = svs + (t & 1) * 160;
        const uint32_t* sa =
            reinterpret_cast<const uint32_t*>(smem + (t % 3) * A_STAGE_BYTES);

        // B fragments: 11 anti-diagonals cover all (ks, nn) pairs
        uint32_t B0[11], B1[11];
#pragma unroll
        for (int d = 0; d < 11; d++) {
            B0[d] = svb[Pl + 8 * d];
            B1[d] = svb[Pl + 8 * d + 4];
        }

#pragma unroll
        for (int ks = 0; ks < 4; ks++) {
            uint32_t a0[4], a1[4];
            const int r0 = (warpM * 32 + g) * A_ROW_WORDS + ks * 8 + tig;
            a0[0] = sa[r0];
            a0[1] = sa[r0 + 8 * A_ROW_WORDS];
            a0[2] = sa[r0 + 4];
            a0[3] = sa[r0 + 8 * A_ROW_WORDS + 4];
            const int r1 = r0 + 16 * A_ROW_WORDS;
            a1[0] = sa[r1];
            a1[1] = sa[r1 + 8 * A_ROW_WORDS];
            a1[2] = sa[r1 + 4];
            a1[3] = sa[r1 + 8 * A_ROW_WORDS + 4];
#pragma unroll
            for (int nn = 0; nn < 8; nn++) {
                const int d = ks - nn + 7;
                mma_tf32(acc[0][nn], a0, B0[d], B1[d]);
                mma_tf32(acc[1][nn], a1, B0[d], B1[d]);
            }
        }
    }

    // epilogue: c0/c1 adjacent columns -> float2 stores
#pragma unroll
    for (int mm = 0; mm < 2; mm++) {
        const int row = m0 + warpM * 32 + mm * 16 + g;
#pragma unroll
        for (int nn = 0; nn < 8; nn++) {
            const int col = n0 + warpN * 64 + nn * 8 + tig * 2;
            *reinterpret_cast<float2*>(out + (size_t)row * N_DIM + col) =
                make_float2(acc[mm][nn][0], acc[mm][nn][1]);
            *reinterpret_cast<float2*>(out + (size_t)(row + 8) * N_DIM + col) =
                make_float2(acc[mm][nn][2], acc[mm][nn][3]);
        }
    }
}

extern "C" void kernel_launch(void* const* d_in, const int* in_sizes, int n_in,
                              void* d_out, int out_size) {
    const float* x    = (const float*)d_in[0];
    const float* vals = (const float*)d_in[1];
    float* out        = (float*)d_out;

    cvt_x_kernel<<<(M_DIM * (size_t)K_DIM) / (256 * 4), 256>>>(x);

    static int attr_set = 0;
    if (!attr_set) {
        cudaFuncSetAttribute(toeplitz_mma_kernel,
                             cudaFuncAttributeMaxDynamicSharedMemorySize,
                             SMEM_TOTAL);
        attr_set = 1;
    }
    dim3 grid(N_DIM / BN, M_DIM / BM);   // 32 x 64
    toeplitz_mma_kernel<<<grid, THREADS, SMEM_TOTAL>>>(vals, out);
}

// round 6
// speedup vs baseline: 1.4358x; 1.1155x over previous
#include <cuda_runtime.h>
#include <cstdint>

// ToeplitzLinear: D[m,n] = sum_k X[m,k] * vals[4095 - n + k]
// tf32 mma.sync (tcgen05 rejected by harness PTX target sm_103).
// R6 = R5 with the B-fragment index bug fixed (spurious -56 removed):
// A pre-shuffled into mma-fragment order (tf32 scratch) -> mainloop A is
// 2x LDS.128 per k-step; vals pre-converted to tf32 -> B frags are L1 LDG hits.

#define M_DIM 8192
#define N_DIM 4096
#define K_DIM 4096
#define BM 128
#define BN 128
#define BK 32
#define NITER (K_DIM / BK)       // 128
#define THREADS 256

#define A_STAGE_BYTES 16384      // 8 rb x 4 cb x 32 lanes x 16B, no padding
#define SMEM_TOTAL (3 * A_STAGE_BYTES)   // 49152

// X in fragment-shuffled tf32 layout:
//   word index = (rb*512 + cb)*128 + lane*4 + j
//   rb = m>>4, cb = k>>3, lane = (g=m&7)*4 + (tig=k&3),
//   j: {(g,tig),(g+8,tig),(g,tig+4),(g+8,tig+4)} = mma.m16n8k8 A-frag order
__device__ uint32_t g_xtf[(size_t)M_DIM * K_DIM];
__device__ uint32_t g_vtf[8192];   // vals as tf32 bits (8191 used)

__device__ __forceinline__ uint32_t f2tf32(float f) {
    uint32_t r;
    asm("cvt.rna.tf32.f32 %0, %1;" : "=r"(r) : "f"(f));
    return r;
}
__device__ __forceinline__ uint32_t smem_u32(const void* p) {
    uint32_t a;
    asm("{ .reg .u64 t; cvta.to.shared.u64 t, %1; cvt.u32.u64 %0, t; }"
        : "=r"(a) : "l"(p));
    return a;
}
__device__ __forceinline__ void cp16(uint32_t saddr, const void* g) {
    asm volatile("cp.async.cg.shared.global [%0], [%1], 16;"
                 :: "r"(saddr), "l"(g) : "memory");
}
__device__ __forceinline__ void cp_commit() {
    asm volatile("cp.async.commit_group;" ::: "memory");
}
template <int N>
__device__ __forceinline__ void cp_wait() {
    asm volatile("cp.async.wait_group %0;" :: "n"(N) : "memory");
}
__device__ __forceinline__ void mma_tf32(float c[4], uint32_t a0, uint32_t a1,
                                         uint32_t a2, uint32_t a3,
                                         uint32_t b0, uint32_t b1) {
    asm volatile(
        "mma.sync.aligned.m16n8k8.row.col.f32.tf32.tf32.f32 "
        "{%0,%1,%2,%3}, {%4,%5,%6,%7}, {%8,%9}, {%0,%1,%2,%3};"
        : "+f"(c[0]), "+f"(c[1]), "+f"(c[2]), "+f"(c[3])
        : "r"(a0), "r"(a1), "r"(a2), "r"(a3), "r"(b0), "r"(b1));
}

// ---- pre-pass: vals -> tf32 ----
__global__ void __launch_bounds__(256) cvt_vals_kernel(const float* __restrict__ v) {
    int i = blockIdx.x * 256 + threadIdx.x;
    if (i < 8191) g_vtf[i] = f2tf32(v[i]);
}

// ---- pre-pass: X -> tf32, fragment-shuffled (smem transpose, coalesced) ----
__global__ void __launch_bounds__(128) cvt_x_kernel(const float* __restrict__ x) {
    __shared__ float sm[16 * 128];
    const int tid = threadIdx.x;
    const int rb = blockIdx.y;            // 0..511 (16-row block)
    const int c0 = blockIdx.x * 128;      // 128-col chunk
#pragma unroll
    for (int i = 0; i < 4; i++) {
        const int f = tid + 128 * i;      // float4 id, 0..511
        const int r = f >> 5;
        const int cq = f & 31;
        float4 v = *reinterpret_cast<const float4*>(
            x + (size_t)(rb * 16 + r) * K_DIM + c0 + cq * 4);
        float* s = sm + r * 128 + cq * 4;
        s[0] = v.x; s[1] = v.y; s[2] = v.z; s[3] = v.w;
    }
    __syncthreads();
#pragma unroll
    for (int i = 0; i < 4; i++) {
        const int gi = tid + 128 * i;     // group id, 0..511
        const int cb = gi >> 5;           // 0..15
        const int lane = gi & 31;
        const int g = lane >> 2;
        const int tig = lane & 3;
        const int cc = cb * 8 + tig;
        uint4 u;
        u.x = f2tf32(sm[g * 128 + cc]);
        u.y = f2tf32(sm[(g + 8) * 128 + cc]);
        u.z = f2tf32(sm[g * 128 + cc + 4]);
        u.w = f2tf32(sm[(g + 8) * 128 + cc + 4]);
        *reinterpret_cast<uint4*>(
            g_xtf + ((size_t)rb * 512 + (c0 >> 3) + cb) * 128 + lane * 4) = u;
    }
}

__device__ __forceinline__ void issue_a(int u, int tid, uint32_t sb, int m0) {
    const uint32_t sbase = sb + (u % 3) * A_STAGE_BYTES;
#pragma unroll
    for (int i = 0; i < 4; i++) {
        const int cid = tid + THREADS * i;          // rbL*128 + cbL*32 + lane
        const int rbL = cid >> 7;
        const int cbL = (cid >> 5) & 3;
        const int lane = cid & 31;
        const void* g = g_xtf +
            ((size_t)((m0 >> 4) + rbL) * 512 + 4 * u + cbL) * 128 + lane * 4;
        cp16(sbase + cid * 16, g);
    }
}

__global__ void __launch_bounds__(THREADS, 2)
toeplitz_mma_kernel(float* __restrict__ out) {
    extern __shared__ char smem[];
    const uint32_t sb = smem_u32(smem);
    const int tid = threadIdx.x;
    const int wid = tid >> 5;
    const int lane = tid & 31;
    const int g = lane >> 2;
    const int tig = lane & 3;
    const int warpM = wid & 3;
    const int warpN = wid >> 2;

    const int n0 = blockIdx.x * BN;   // n fastest -> X tile L2 reuse
    const int m0 = blockIdx.y * BM;
    const int vbase = 3968 - n0;

    float acc[2][8][4];
#pragma unroll
    for (int mm = 0; mm < 2; mm++)
#pragma unroll
        for (int nn = 0; nn < 8; nn++)
#pragma unroll
            for (int r = 0; r < 4; r++) acc[mm][nn][r] = 0.0f;

    issue_a(0, tid, sb, m0);
    cp_commit();
    issue_a(1, tid, sb, m0);
    cp_commit();

    // Toeplitz B-frag base: bi(ks,nn) = Pl + 8*d, d = ks-nn+7 in [0,10],
    // Pl in [0,74], window index Pl+8d+4 <= 158 (verified R4-correct form)
    const int Pl = tig - g + 71 - warpN * 64;

#pragma unroll 1
    for (int t = 0; t < NITER; t++) {
        cp_wait<1>();
        __syncthreads();
        if (t + 2 < NITER) issue_a(t + 2, tid, sb, m0);
        cp_commit();

        // B fragments: 11 anti-diagonals, L1-resident LDGs
        const uint32_t* vp = g_vtf + vbase + 32 * t + Pl;
        uint32_t B0[11], B1[11];
#pragma unroll
        for (int d = 0; d < 11; d++) {
            B0[d] = __ldg(vp + 8 * d);
            B1[d] = __ldg(vp + 8 * d + 4);
        }

#pragma unroll
        for (int ks = 0; ks < 4; ks++) {
            uint4 A0 = *reinterpret_cast<const uint4*>(
                smem + (t % 3) * A_STAGE_BYTES +
                (((warpM * 2 + 0) * 4 + ks) * 32 + lane) * 16);
            uint4 A1 = *reinterpret_cast<const uint4*>(
                smem + (t % 3) * A_STAGE_BYTES +
                (((warpM * 2 + 1) * 4 + ks) * 32 + lane) * 16);
#pragma unroll
            for (int nn = 0; nn < 8; nn++) {
                const int d = ks - nn + 7;
                mma_tf32(acc[0][nn], A0.x, A0.y, A0.z, A0.w, B0[d], B1[d]);
                mma_tf32(acc[1][nn], A1.x, A1.y, A1.z, A1.w, B0[d], B1[d]);
            }
        }
    }

    // epilogue: c0/c1 adjacent columns -> float2 stores
#pragma unroll
    for (int mm = 0; mm < 2; mm++) {
        const int row = m0 + warpM * 32 + mm * 16 + g;
#pragma unroll
        for (int nn = 0; nn < 8; nn++) {
            const int col = n0 + warpN * 64 + nn * 8 + tig * 2;
            *reinterpret_cast<float2*>(out + (size_t)row * N_DIM + col) =
                make_float2(acc[mm][nn][0], acc[mm][nn][1]);
            *reinterpret_cast<float2*>(out + (size_t)(row + 8) * N_DIM + col) =
                make_float2(acc[mm][nn][2], acc[mm][nn][3]);
        }
    }
}

extern "C" void kernel_launch(void* const* d_in, const int* in_sizes, int n_in,
                              void* d_out, int out_size) {
    const float* x    = (const float*)d_in[0];
    const float* vals = (const float*)d_in[1];
    float* out        = (float*)d_out;

    cvt_vals_kernel<<<32, 256>>>(vals);
    cvt_x_kernel<<<dim3(K_DIM / 128, M_DIM / 16), 128>>>(x);

    dim3 grid(N_DIM / BN, M_DIM / BM);   // 32 x 64
    toeplitz_mma_kernel<<<grid, THREADS, SMEM_TOTAL>>>(out);
}

// round 7
// speedup vs baseline: 2.6284x; 1.8307x over previous
#include <cuda_runtime.h>
#include <cuda_fp16.h>
#include <cstdint>

// ToeplitzLinear: D[m,n] = sum_k X[m,k] * vals[4095 - n + k]
// R7: fp16 mma.m16n8k16 (same 10-bit mantissa as tf32 -> same ~3e-4 rel_err,
// 2x FLOP rate). A pre-shuffled fp16 fragments in gmem scratch; B fragments
// from a half2-pair table (handles odd k-offsets with one aligned LDG.32).

#define M_DIM 8192
#define N_DIM 4096
#define K_DIM 4096
#define BM 128
#define BN 128
#define BK 32
#define NITER (K_DIM / BK)       // 128
#define THREADS 256

#define A_STAGE_BYTES 8192       // 8 rb x 2 cb x 128 half2-words x 4B
#define SMEM_TOTAL (3 * A_STAGE_BYTES)   // 24576

// X as fp16 in m16n8k16-fragment order:
//   word idx = (rb*256 + cb)*128 + lane*4 + j,  rb=m>>4, cb=k>>4
//   lane = (g=m&7... ) g*4+tig; j=0:(g,2tig|+1) j=1:(g+8,..) j=2:(g,2tig+8|+9) j=3:(g+8,..)
__device__ uint32_t g_xh[(size_t)M_DIM * K_DIM / 2];
__device__ uint32_t g_v2h[8192];   // g_v2h[i] = half2(w[i], w[i+1]), w = fp16(vals)

__device__ __forceinline__ uint32_t smem_u32(const void* p) {
    uint32_t a;
    asm("{ .reg .u64 t; cvta.to.shared.u64 t, %1; cvt.u32.u64 %0, t; }"
        : "=r"(a) : "l"(p));
    return a;
}
__device__ __forceinline__ void cp16(uint32_t saddr, const void* g) {
    asm volatile("cp.async.cg.shared.global [%0], [%1], 16;"
                 :: "r"(saddr), "l"(g) : "memory");
}
__device__ __forceinline__ void cp_commit() {
    asm volatile("cp.async.commit_group;" ::: "memory");
}
template <int N>
__device__ __forceinline__ void cp_wait() {
    asm volatile("cp.async.wait_group %0;" :: "n"(N) : "memory");
}
__device__ __forceinline__ void mma_fp16(float c[4], uint32_t a0, uint32_t a1,
                                         uint32_t a2, uint32_t a3,
                                         uint32_t b0, uint32_t b1) {
    asm volatile(
        "mma.sync.aligned.m16n8k16.row.col.f32.f16.f16.f32 "
        "{%0,%1,%2,%3}, {%4,%5,%6,%7}, {%8,%9}, {%0,%1,%2,%3};"
        : "+f"(c[0]), "+f"(c[1]), "+f"(c[2]), "+f"(c[3])
        : "r"(a0), "r"(a1), "r"(a2), "r"(a3), "r"(b0), "r"(b1));
}

// ---- pre-pass: vals -> fp16 pair table ----
__global__ void __launch_bounds__(256) cvt_vals_kernel(const float* __restrict__ v) {
    int i = blockIdx.x * 256 + threadIdx.x;   // grid covers 8192
    if (i < 8192) {
        float a = (i < 8191) ? v[i] : 0.0f;
        float b = (i + 1 < 8191) ? v[i + 1] : 0.0f;
        __half2 h = __floats2half2_rn(a, b);
        g_v2h[i] = *reinterpret_cast<uint32_t*>(&h);
    }
}

// ---- pre-pass: X -> fp16, m16n8k16-fragment-shuffled ----
__global__ void __launch_bounds__(128) cvt_x_kernel(const float* __restrict__ x) {
    __shared__ float sm[16 * 128];
    const int tid = threadIdx.x;
    const int rb = blockIdx.y;            // 0..511 (16-row block)
    const int c0 = blockIdx.x * 128;      // 128-col chunk (8 cbs)
#pragma unroll
    for (int i = 0; i < 4; i++) {
        const int f = tid + 128 * i;      // float4 id 0..511
        const int r = f >> 5;
        const int cq = f & 31;
        float4 v = *reinterpret_cast<const float4*>(
            x + (size_t)(rb * 16 + r) * K_DIM + c0 + cq * 4);
        float* s = sm + r * 128 + cq * 4;
        s[0] = v.x; s[1] = v.y; s[2] = v.z; s[3] = v.w;
    }
    __syncthreads();
    // 8 cb x 128 words = 512 uint2 (word pairs j,j+1 for even j)
#pragma unroll
    for (int i = 0; i < 4; i++) {
        const int p = tid + 128 * i;      // 0..511
        const int cbL = p >> 6;           // 0..7
        const int pw = p & 63;
        const int widx = pw * 2;          // even word index 0..126
        const int lane = widx >> 2;
        const int j = widx & 3;           // 0 or 2
        const int g = lane >> 2;
        const int tig = lane & 3;
        const int k = cbL * 16 + 2 * tig + (j >> 1) * 8;
        __half2 lo = __floats2half2_rn(sm[g * 128 + k], sm[g * 128 + k + 1]);
        __half2 hi = __floats2half2_rn(sm[(g + 8) * 128 + k], sm[(g + 8) * 128 + k + 1]);
        uint2 u;
        u.x = *reinterpret_cast<uint32_t*>(&lo);
        u.y = *reinterpret_cast<uint32_t*>(&hi);
        *reinterpret_cast<uint2*>(
            g_xh + ((size_t)rb * 256 + (c0 >> 4) + cbL) * 128 + widx) = u;
    }
}

__device__ __forceinline__ void issue_a(int u, int tid, uint32_t sb, int m0) {
    const uint32_t sbase = sb + (u % 3) * A_STAGE_BYTES;
#pragma unroll
    for (int i = 0; i < 2; i++) {
        const int cid = tid + THREADS * i;        // 0..511 16B-chunks
        const int rbL = cid >> 6;                 // 0..7
        const int cbL = (cid >> 5) & 1;           // 0..1
        const int ch = cid & 31;                  // chunk within (rb,cb)
        const void* g = g_xh +
            ((size_t)((m0 >> 4) + rbL) * 256 + 2 * u + cbL) * 128 + ch * 4;
        cp16(sbase + cid * 16, g);
    }
}

__global__ void __launch_bounds__(THREADS, 2)
toeplitz_mma_kernel(float* __restrict__ out) {
    extern __shared__ char smem[];
    const uint32_t sb = smem_u32(smem);
    const int tid = threadIdx.x;
    const int wid = tid >> 5;
    const int lane = tid & 31;
    const int g = lane >> 2;
    const int tig = lane & 3;
    const int warpM = wid & 3;
    const int warpN = wid >> 2;

    const int n0 = blockIdx.x * BN;   // n fastest -> X tile L2 reuse
    const int m0 = blockIdx.y * BM;
    const int vbase = 3968 - n0;      // window t = g_v2h[vbase + 32t + s]

    float acc[2][8][4];
#pragma unroll
    for (int mm = 0; mm < 2; mm++)
#pragma unroll
        for (int nn = 0; nn < 8; nn++)
#pragma unroll
            for (int r = 0; r < 4; r++) acc[mm][nn][r] = 0.0f;

    issue_a(0, tid, sb, m0);
    cp_commit();
    issue_a(1, tid, sb, m0);
    cp_commit();

    // B-frag index: b0 at s = Q + 8e, b1 at s+8, e = 2ks-nn+7 in [0,9]
    // Q in [0,77]; window idx <= 158; global idx in [0,8190] for all CTAs
    const int Q = 2 * tig - g + 71 - warpN * 64;

#pragma unroll 1
    for (int t = 0; t < NITER; t++) {
        cp_wait<1>();
        __syncthreads();
        if (t + 2 < NITER) issue_a(t + 2, tid, sb, m0);
        cp_commit();

        // 11 diagonal B fragments (L1-resident LDG.32 of half2 pairs)
        const uint32_t* vp = g_v2h + vbase + 32 * t + Q;
        uint32_t Bf[11];
#pragma unroll
        for (int e = 0; e < 11; e++) Bf[e] = __ldg(vp + 8 * e);

#pragma unroll
        for (int ks = 0; ks < 2; ks++) {
            uint4 A0 = *reinterpret_cast<const uint4*>(
                smem + (t % 3) * A_STAGE_BYTES +
                (((warpM * 2 + 0) * 2 + ks) * 32 + lane) * 16);
            uint4 A1 = *reinterpret_cast<const uint4*>(
                smem + (t % 3) * A_STAGE_BYTES +
                (((warpM * 2 + 1) * 2 + ks) * 32 + lane) * 16);
#pragma unroll
            for (int nn = 0; nn < 8; nn++) {
                const int e = 2 * ks - nn + 7;
                mma_fp16(acc[0][nn], A0.x, A0.y, A0.z, A0.w, Bf[e], Bf[e + 1]);
                mma_fp16(acc[1][nn], A1.x, A1.y, A1.z, A1.w, Bf[e], Bf[e + 1]);
            }
        }
    }

    // epilogue: c0/c1 adjacent columns -> float2 stores
#pragma unroll
    for (int mm = 0; mm < 2; mm++) {
        const int row = m0 + warpM * 32 + mm * 16 + g;
#pragma unroll
        for (int nn = 0; nn < 8; nn++) {
            const int col = n0 + warpN * 64 + nn * 8 + tig * 2;
            *reinterpret_cast<float2*>(out + (size_t)row * N_DIM + col) =
                make_float2(acc[mm][nn][0], acc[mm][nn][1]);
            *reinterpret_cast<float2*>(out + (size_t)(row + 8) * N_DIM + col) =
                make_float2(acc[mm][nn][2], acc[mm][nn][3]);
        }
    }
}

extern "C" void kernel_launch(void* const* d_in, const int* in_sizes, int n_in,
                              void* d_out, int out_size) {
    const float* x    = (const float*)d_in[0];
    const float* vals = (const float*)d_in[1];
    float* out        = (float*)d_out;

    cvt_vals_kernel<<<32, 256>>>(vals);
    cvt_x_kernel<<<dim3(K_DIM / 128, M_DIM / 16), 128>>>(x);

    dim3 grid(N_DIM / BN, M_DIM / BM);   // 32 x 64
    toeplitz_mma_kernel<<<grid, THREADS, SMEM_TOTAL>>>(out);
}

// round 8
// speedup vs baseline: 2.7694x; 1.0536x over previous
#include <cuda_runtime.h>
#include <cuda_fp16.h>
#include <cstdint>

// ToeplitzLinear: D[m,n] = sum_k X[m,k] * vals[4095 - n + k]
// R8: fp16 m16n8k16 with BK=64 (half the loop iterations -> half the
// barrier/commit/setup overhead per HMMA). A pre-shuffled fp16 fragments in
// gmem scratch; B fragments from half2-pair table (15 L1-hit LDG.32/iter).

#define M_DIM 8192
#define N_DIM 4096
#define K_DIM 4096
#define BM 128
#define BN 128
#define BK 64
#define NITER (K_DIM / BK)       // 64
#define THREADS 256

#define A_STAGE_BYTES 16384      // 8 rb x 4 cb x 128 words x 4B
#define SMEM_TOTAL (3 * A_STAGE_BYTES)   // 49152

// X as fp16 in m16n8k16-fragment order:
//   word idx = (rb*256 + cb)*128 + lane*4 + j,  rb=m>>4, cb=k>>4
__device__ uint32_t g_xh[(size_t)M_DIM * K_DIM / 2];
__device__ uint32_t g_v2h[8192];   // g_v2h[i] = half2(w[i], w[i+1]), w = fp16(vals)

__device__ __forceinline__ uint32_t smem_u32(const void* p) {
    uint32_t a;
    asm("{ .reg .u64 t; cvta.to.shared.u64 t, %1; cvt.u32.u64 %0, t; }"
        : "=r"(a) : "l"(p));
    return a;
}
__device__ __forceinline__ void cp16(uint32_t saddr, const void* g) {
    asm volatile("cp.async.cg.shared.global [%0], [%1], 16;"
                 :: "r"(saddr), "l"(g) : "memory");
}
__device__ __forceinline__ void cp_commit() {
    asm volatile("cp.async.commit_group;" ::: "memory");
}
template <int N>
__device__ __forceinline__ void cp_wait() {
    asm volatile("cp.async.wait_group %0;" :: "n"(N) : "memory");
}
__device__ __forceinline__ void mma_fp16(float c[4], uint32_t a0, uint32_t a1,
                                         uint32_t a2, uint32_t a3,
                                         uint32_t b0, uint32_t b1) {
    asm volatile(
        "mma.sync.aligned.m16n8k16.row.col.f32.f16.f16.f32 "
        "{%0,%1,%2,%3}, {%4,%5,%6,%7}, {%8,%9}, {%0,%1,%2,%3};"
        : "+f"(c[0]), "+f"(c[1]), "+f"(c[2]), "+f"(c[3])
        : "r"(a0), "r"(a1), "r"(a2), "r"(a3), "r"(b0), "r"(b1));
}

// ---- pre-pass: vals -> fp16 pair table ----
__global__ void __launch_bounds__(256) cvt_vals_kernel(const float* __restrict__ v) {
    int i = blockIdx.x * 256 + threadIdx.x;
    if (i < 8192) {
        float a = (i < 8191) ? v[i] : 0.0f;
        float b = (i + 1 < 8191) ? v[i + 1] : 0.0f;
        __half2 h = __floats2half2_rn(a, b);
        g_v2h[i] = *reinterpret_cast<uint32_t*>(&h);
    }
}

// ---- pre-pass: X -> fp16, m16n8k16-fragment-shuffled ----
__global__ void __launch_bounds__(128) cvt_x_kernel(const float* __restrict__ x) {
    __shared__ float sm[16 * 128];
    const int tid = threadIdx.x;
    const int rb = blockIdx.y;            // 0..511 (16-row block)
    const int c0 = blockIdx.x * 128;      // 128-col chunk (8 cbs)
#pragma unroll
    for (int i = 0; i < 4; i++) {
        const int f = tid + 128 * i;      // float4 id 0..511
        const int r = f >> 5;
        const int cq = f & 31;
        float4 v = *reinterpret_cast<const float4*>(
            x + (size_t)(rb * 16 + r) * K_DIM + c0 + cq * 4);
        float* s = sm + r * 128 + cq * 4;
        s[0] = v.x; s[1] = v.y; s[2] = v.z; s[3] = v.w;
    }
    __syncthreads();
#pragma unroll
    for (int i = 0; i < 4; i++) {
        const int p = tid + 128 * i;      // 0..511
        const int cbL = p >> 6;           // 0..7
        const int pw = p & 63;
        const int widx = pw * 2;          // even word index
        const int lane = widx >> 2;
        const int j = widx & 3;           // 0 or 2
        const int g = lane >> 2;
        const int tig = lane & 3;
        const int k = cbL * 16 + 2 * tig + (j >> 1) * 8;
        __half2 lo = __floats2half2_rn(sm[g * 128 + k], sm[g * 128 + k + 1]);
        __half2 hi = __floats2half2_rn(sm[(g + 8) * 128 + k], sm[(g + 8) * 128 + k + 1]);
        uint2 u;
        u.x = *reinterpret_cast<uint32_t*>(&lo);
        u.y = *reinterpret_cast<uint32_t*>(&hi);
        *reinterpret_cast<uint2*>(
            g_xh + ((size_t)rb * 256 + (c0 >> 4) + cbL) * 128 + widx) = u;
    }
}

__device__ __forceinline__ void issue_a(int u, int tid, uint32_t sb, int m0) {
    const uint32_t sbase = sb + (u % 3) * A_STAGE_BYTES;
#pragma unroll
    for (int i = 0; i < 4; i++) {
        const int cid = tid + THREADS * i;        // 0..1023 16B-chunks
        const int rbL = cid >> 7;                 // 0..7
        const int cbL = (cid >> 5) & 3;           // 0..3
        const int ch = cid & 31;
        const void* g = g_xh +
            ((size_t)((m0 >> 4) + rbL) * 256 + 4 * u + cbL) * 128 + ch * 4;
        cp16(sbase + cid * 16, g);
    }
}

__global__ void __launch_bounds__(THREADS, 2)
toeplitz_mma_kernel(float* __restrict__ out) {
    extern __shared__ char smem[];
    const uint32_t sb = smem_u32(smem);
    const int tid = threadIdx.x;
    const int wid = tid >> 5;
    const int lane = tid & 31;
    const int g = lane >> 2;
    const int tig = lane & 3;
    const int warpM = wid & 3;
    const int warpN = wid >> 2;

    const int n0 = blockIdx.x * BN;   // n fastest -> X tile L2 reuse
    const int m0 = blockIdx.y * BM;
    const int vbase = 3968 - n0;      // window t = g_v2h[vbase + 64t + s]

    float acc[2][8][4];
#pragma unroll
    for (int mm = 0; mm < 2; mm++)
#pragma unroll
        for (int nn = 0; nn < 8; nn++)
#pragma unroll
            for (int r = 0; r < 4; r++) acc[mm][nn][r] = 0.0f;

    issue_a(0, tid, sb, m0);
    cp_commit();
    issue_a(1, tid, sb, m0);
    cp_commit();

    // B-frag: b0 at s = Q + 8e, b1 at s+8, e = 2ks-nn+7 in [0,13]
    // Q in [0,77], s+8 <= 189+.. <= 190; global idx in [0,8190] for all CTAs
    const int Q = 2 * tig - g + 71 - warpN * 64;

#pragma unroll 1
    for (int t = 0; t < NITER; t++) {
        cp_wait<1>();
        __syncthreads();
        if (t + 2 < NITER) issue_a(t + 2, tid, sb, m0);
        cp_commit();

        // 15 diagonal B fragments (L1-resident LDG.32 of half2 pairs)
        const uint32_t* vp = g_v2h + vbase + 64 * t + Q;
        uint32_t Bf[15];
#pragma unroll
        for (int e = 0; e < 15; e++) Bf[e] = __ldg(vp + 8 * e);

        const char* sA = smem + (t % 3) * A_STAGE_BYTES;
#pragma unroll
        for (int ks = 0; ks < 4; ks++) {
            uint4 A0 = *reinterpret_cast<const uint4*>(
                sA + (((warpM * 2 + 0) * 4 + ks) * 32 + lane) * 16);
            uint4 A1 = *reinterpret_cast<const uint4*>(
                sA + (((warpM * 2 + 1) * 4 + ks) * 32 + lane) * 16);
#pragma unroll
            for (int nn = 0; nn < 8; nn++) {
                const int e = 2 * ks - nn + 7;
                mma_fp16(acc[0][nn], A0.x, A0.y, A0.z, A0.w, Bf[e], Bf[e + 1]);
                mma_fp16(acc[1][nn], A1.x, A1.y, A1.z, A1.w, Bf[e], Bf[e + 1]);
            }
        }
    }

    // epilogue: c0/c1 adjacent columns -> float2 stores
#pragma unroll
    for (int mm = 0; mm < 2; mm++) {
        const int row = m0 + warpM * 32 + mm * 16 + g;
#pragma unroll
        for (int nn = 0; nn < 8; nn++) {
            const int col = n0 + warpN * 64 + nn * 8 + tig * 2;
            *reinterpret_cast<float2*>(out + (size_t)row * N_DIM + col) =
                make_float2(acc[mm][nn][0], acc[mm][nn][1]);
            *reinterpret_cast<float2*>(out + (size_t)(row + 8) * N_DIM + col) =
                make_float2(acc[mm][nn][2], acc[mm][nn][3]);
        }
    }
}

extern "C" void kernel_launch(void* const* d_in, const int* in_sizes, int n_in,
                              void* d_out, int out_size) {
    const float* x    = (const float*)d_in[0];
    const float* vals = (const float*)d_in[1];
    float* out        = (float*)d_out;

    cvt_vals_kernel<<<32, 256>>>(vals);
    cvt_x_kernel<<<dim3(K_DIM / 128, M_DIM / 16), 128>>>(x);

    dim3 grid(N_DIM / BN, M_DIM / BM);   // 32 x 64
    toeplitz_mma_kernel<<<grid, THREADS, SMEM_TOTAL>>>(out);
}